// round 5
// baseline (speedup 1.0000x reference)
#include <cuda_runtime.h>

#define C_  8
#define NQ_ 16
#define NK_ 32
#define B_  128
#define D_  128
#define E_  512
#define H_  8
#define A_  64
#define O_  64

// Scratch (device globals — allocation-free per harness rules).
// g_query doubles as the attention-output buffer: each attn block reads and
// writes exactly the same disjoint (c,b,h,q,a) slice, reads staged to smem first.
__device__ float g_query[C_*NQ_*B_*E_];
__device__ float g_key  [C_*NK_*B_*E_];
__device__ float g_value[C_*NK_*B_*E_];

// ---------------------------------------------------------------------------
// Grouped GEMM with optional sinusoidal PE added to the A operand.
// Y[g][m][n] = sum_d (X[g][m][d] (+ pe(slot,d))) * W[g][d][n]
// X:(G,B,D)  W:(G,D,E)  Y:(G,B,E).  Tile 128x128, BK=16, 256 thr, 8x8 micro.
// grid: (E/128, G)
// ---------------------------------------------------------------------------
template<bool PE>
__global__ void __launch_bounds__(256) proj_kernel(
    const float* __restrict__ X, const float* __restrict__ W,
    float* __restrict__ Y, int nslots)
{
  const int g  = blockIdx.y;
  const int n0 = blockIdx.x * 128;
  const float* Xg = X + (size_t)g * (B_*D_);
  const float* Wg = W + (size_t)g * (D_*E_);
  float*       Yg = Y + (size_t)g * (B_*E_);

  __shared__ float pe_s[D_];
  __shared__ float As[16][132];   // transposed A tile, padded
  __shared__ float Bs[16][128];

  const int tid = threadIdx.x;
  if (PE) {
    if (tid < D_) {
      const int slot = g % nslots;
      const int i = tid >> 1;
      // div[i] = exp(2i * (-ln(10000)/D));  pe[2i]=sin, pe[2i+1]=cos
      float freq = expf((float)(2*i) * (-9.210340371976184f / (float)D_));
      float ang  = (float)slot * freq;
      pe_s[tid] = (tid & 1) ? cosf(ang) : sinf(ang);
    }
    __syncthreads();
  }

  const int tx = tid & 15;
  const int ty = tid >> 4;

  float acc[8][8];
  #pragma unroll
  for (int i = 0; i < 8; ++i)
    #pragma unroll
    for (int j = 0; j < 8; ++j) acc[i][j] = 0.f;

  for (int k0 = 0; k0 < D_; k0 += 16) {
    // A tile: 128 rows x 16 cols = 512 float4, 2 per thread, store transposed
    #pragma unroll
    for (int r = 0; r < 2; ++r) {
      int idx = tid + r*256;
      int row = idx >> 2;
      int c4  = (idx & 3) << 2;
      float4 v = *reinterpret_cast<const float4*>(Xg + row*D_ + k0 + c4);
      if (PE) {
        v.x += pe_s[k0+c4+0]; v.y += pe_s[k0+c4+1];
        v.z += pe_s[k0+c4+2]; v.w += pe_s[k0+c4+3];
      }
      As[c4+0][row]=v.x; As[c4+1][row]=v.y; As[c4+2][row]=v.z; As[c4+3][row]=v.w;
    }
    // B tile: 16 rows x 128 cols = 512 float4, 2 per thread
    #pragma unroll
    for (int r = 0; r < 2; ++r) {
      int idx = tid + r*256;
      int row = idx >> 5;
      int c4  = (idx & 31) << 2;
      *reinterpret_cast<float4*>(&Bs[row][c4]) =
          *reinterpret_cast<const float4*>(Wg + (size_t)(k0+row)*E_ + n0 + c4);
    }
    __syncthreads();

    #pragma unroll
    for (int kk = 0; kk < 16; ++kk) {
      float a[8], b[8];
      #pragma unroll
      for (int i = 0; i < 8; ++i) a[i] = As[kk][ty*8+i];
      #pragma unroll
      for (int j = 0; j < 8; ++j) b[j] = Bs[kk][tx*8+j];
      #pragma unroll
      for (int i = 0; i < 8; ++i)
        #pragma unroll
        for (int j = 0; j < 8; ++j) acc[i][j] += a[i]*b[j];
    }
    __syncthreads();
  }

  #pragma unroll
  for (int i = 0; i < 8; ++i) {
    int m = ty*8 + i;
    #pragma unroll
    for (int j = 0; j < 8; j += 4) {
      *reinterpret_cast<float4*>(Yg + (size_t)m*E_ + n0 + tx*8 + j) =
          make_float4(acc[i][j], acc[i][j+1], acc[i][j+2], acc[i][j+3]);
    }
  }
}

// ---------------------------------------------------------------------------
// Fused attention: one block per (c,b,h). logits -> softmax -> P@V.
// Writes results back over the query slice it consumed (block-disjoint).
// ---------------------------------------------------------------------------
__global__ void __launch_bounds__(128) attn_kernel(
    float* __restrict__ Q,              // in: query, out: attention output
    const float* __restrict__ K, const float* __restrict__ V)
{
  const int idx = blockIdx.x;           // ((c*B + b)*H + h)
  const int h = idx & (H_-1);
  const int b = (idx >> 3) & (B_-1);
  const int c = idx >> 10;

  __shared__ float Qs[NQ_][65];
  __shared__ float Ks[NK_][65];
  __shared__ float Vs[NK_][65];
  __shared__ float Ls[NQ_][33];

  const int tid = threadIdx.x;

  // Q: 16 rows x 64 = 256 float4 (2/thread)
  #pragma unroll
  for (int r = 0; r < 2; ++r) {
    int i = tid + r*128;
    int row = i >> 4;
    int c4  = (i & 15) << 2;
    const float* src = Q + ((size_t)((c*NQ_+row)*B_ + b))*E_ + h*A_ + c4;
    float4 v = *reinterpret_cast<const float4*>(src);
    Qs[row][c4+0]=v.x; Qs[row][c4+1]=v.y; Qs[row][c4+2]=v.z; Qs[row][c4+3]=v.w;
  }
  // K, V: 32 rows x 64 = 512 float4 each (4/thread)
  #pragma unroll
  for (int r = 0; r < 4; ++r) {
    int i = tid + r*128;
    int row = i >> 4;
    int c4  = (i & 15) << 2;
    size_t off = ((size_t)((c*NK_+row)*B_ + b))*E_ + h*A_ + c4;
    float4 v = *reinterpret_cast<const float4*>(K + off);
    Ks[row][c4+0]=v.x; Ks[row][c4+1]=v.y; Ks[row][c4+2]=v.z; Ks[row][c4+3]=v.w;
    float4 w = *reinterpret_cast<const float4*>(V + off);
    Vs[row][c4+0]=w.x; Vs[row][c4+1]=w.y; Vs[row][c4+2]=w.z; Vs[row][c4+3]=w.w;
  }
  __syncthreads();

  // logits[q][k] = (1/sqrt(A)) * <Qs[q], Ks[k]>
  {
    const int q  = tid >> 3;
    const int kg = tid & 7;
    float s0=0.f, s1=0.f, s2=0.f, s3=0.f;
    #pragma unroll
    for (int a = 0; a < A_; ++a) {
      float qa = Qs[q][a];
      s0 += qa * Ks[kg     ][a];
      s1 += qa * Ks[kg +  8][a];
      s2 += qa * Ks[kg + 16][a];
      s3 += qa * Ks[kg + 24][a];
    }
    const float it = 0.125f;   // 1/sqrt(64)
    Ls[q][kg   ] = s0*it;
    Ls[q][kg+ 8] = s1*it;
    Ls[q][kg+16] = s2*it;
    Ls[q][kg+24] = s3*it;
  }
  __syncthreads();

  // softmax over k, one thread per query row
  if (tid < NQ_) {
    float m = -1e30f;
    #pragma unroll
    for (int j = 0; j < NK_; ++j) m = fmaxf(m, Ls[tid][j]);
    float s = 0.f;
    #pragma unroll
    for (int j = 0; j < NK_; ++j) { float e = expf(Ls[tid][j]-m); Ls[tid][j]=e; s+=e; }
    float inv = 1.f/s;
    #pragma unroll
    for (int j = 0; j < NK_; ++j) Ls[tid][j] *= inv;
  }
  __syncthreads();

  // out[q][a] = sum_k P[q][k] * V[k][a]
  {
    const int q  = tid >> 3;
    const int a0 = (tid & 7) << 3;
    float acc[8];
    #pragma unroll
    for (int j = 0; j < 8; ++j) acc[j] = 0.f;
    #pragma unroll
    for (int kk = 0; kk < NK_; ++kk) {
      float p = Ls[q][kk];
      #pragma unroll
      for (int j = 0; j < 8; ++j) acc[j] += p * Vs[kk][a0+j];
    }
    float* dst = Q + ((size_t)((c*NQ_+q)*B_ + b))*E_ + h*A_ + a0;
    *reinterpret_cast<float4*>(dst+0) = make_float4(acc[0],acc[1],acc[2],acc[3]);
    *reinterpret_cast<float4*>(dst+4) = make_float4(acc[4],acc[5],acc[6],acc[7]);
  }
}

// ---------------------------------------------------------------------------
// Output projection: per (c,q): (128x512)@(512x64). 256 thr, 8x4 micro.
// ---------------------------------------------------------------------------
__global__ void __launch_bounds__(256) outproj_kernel(
    const float* __restrict__ Xa, const float* __restrict__ Wp,
    float* __restrict__ Y)
{
  const int g = blockIdx.x;                       // C*NQ
  const float* Ag = Xa + (size_t)g * (B_*E_);
  const float* Wg = Wp + (size_t)g * (E_*O_);
  float*       Yg = Y  + (size_t)g * (B_*O_);

  __shared__ float As[16][132];
  __shared__ float Bs[16][64];

  const int tid = threadIdx.x;
  const int tx = tid & 15;
  const int ty = tid >> 4;

  float acc[8][4];
  #pragma unroll
  for (int i = 0; i < 8; ++i)
    #pragma unroll
    for (int j = 0; j < 4; ++j) acc[i][j] = 0.f;

  for (int k0 = 0; k0 < E_; k0 += 16) {
    #pragma unroll
    for (int r = 0; r < 2; ++r) {
      int idx = tid + r*256;
      int row = idx >> 2;
      int c4  = (idx & 3) << 2;
      float4 v = *reinterpret_cast<const float4*>(Ag + (size_t)row*E_ + k0 + c4);
      As[c4+0][row]=v.x; As[c4+1][row]=v.y; As[c4+2][row]=v.z; As[c4+3][row]=v.w;
    }
    {
      int row = tid >> 4;
      int c4  = (tid & 15) << 2;
      *reinterpret_cast<float4*>(&Bs[row][c4]) =
          *reinterpret_cast<const float4*>(Wg + (size_t)(k0+row)*O_ + c4);
    }
    __syncthreads();

    #pragma unroll
    for (int kk = 0; kk < 16; ++kk) {
      float a[8], bb[4];
      #pragma unroll
      for (int i = 0; i < 8; ++i) a[i]  = As[kk][ty*8+i];
      #pragma unroll
      for (int j = 0; j < 4; ++j) bb[j] = Bs[kk][tx*4+j];
      #pragma unroll
      for (int i = 0; i < 8; ++i)
        #pragma unroll
        for (int j = 0; j < 4; ++j) acc[i][j] += a[i]*bb[j];
    }
    __syncthreads();
  }

  #pragma unroll
  for (int i = 0; i < 8; ++i) {
    int m = ty*8 + i;
    *reinterpret_cast<float4*>(Yg + (size_t)m*O_ + tx*4) =
        make_float4(acc[i][0], acc[i][1], acc[i][2], acc[i][3]);
  }
}

extern "C" void kernel_launch(void* const* d_in, const int* in_sizes, int n_in,
                              void* d_out, int out_size)
{
  const float* q  = (const float*)d_in[0];
  const float* k  = (const float*)d_in[1];
  const float* Wq = (const float*)d_in[2];
  const float* Wk = (const float*)d_in[3];
  const float* Wv = (const float*)d_in[4];
  const float* Wp = (const float*)d_in[5];
  float* out = (float*)d_out;

  float *gq, *gk, *gv;
  cudaGetSymbolAddress((void**)&gq, g_query);
  cudaGetSymbolAddress((void**)&gk, g_key);
  cudaGetSymbolAddress((void**)&gv, g_value);

  proj_kernel<true><<<dim3(4, C_*NQ_), 256>>>(q, Wq, gq, NQ_);
  proj_kernel<true><<<dim3(4, C_*NK_), 256>>>(k, Wk, gk, NK_);
  proj_kernel<true><<<dim3(4, C_*NK_), 256>>>(k, Wv, gv, NK_);
  attn_kernel<<<C_*B_*H_, 128>>>(gq, gk, gv);
  outproj_kernel<<<C_*NQ_, 256>>>(gq, Wp, out);
}

// round 8
// speedup vs baseline: 1.1400x; 1.1400x over previous
#include <cuda_runtime.h>

#define C_  8
#define NQ_ 16
#define NK_ 32
#define B_  128
#define D_  128
#define E_  512
#define H_  8
#define A_  64
#define O_  64

// Scratch (device globals — allocation-free per harness rules).
// g_query doubles as the attention-output buffer: each attn block reads and
// writes exactly the same disjoint (c,b,h,q,a) slice, reads staged to smem first.
__device__ float g_query[C_*NQ_*B_*E_];
__device__ float g_key  [C_*NK_*B_*E_];
__device__ float g_value[C_*NK_*B_*E_];

// ---------------------------------------------------------------------------
// Grouped GEMM with optional sinusoidal PE added to the A operand.
// Y[g][m][n] = sum_d (X[g][m][d] (+ pe(slot,d))) * W[g][d][n]
// X:(G,B,D)  W:(G,D,E)  Y:(G,B,E).  Tile 128x128, BK=16, 256 thr, 8x8 micro.
// grid: (E/128, G)
// ---------------------------------------------------------------------------
template<bool PE>
__global__ void __launch_bounds__(256) proj_kernel(
    const float* __restrict__ X, const float* __restrict__ W,
    float* __restrict__ Y, int nslots)
{
  const int g  = blockIdx.y;
  const int n0 = blockIdx.x * 128;
  const float* Xg = X + (size_t)g * (B_*D_);
  const float* Wg = W + (size_t)g * (D_*E_);
  float*       Yg = Y + (size_t)g * (B_*E_);

  __shared__ float pe_s[D_];
  __shared__ float As[16][132];   // transposed A tile, padded
  __shared__ float Bs[16][128];

  const int tid = threadIdx.x;
  if (PE) {
    if (tid < D_) {
      const int slot = g % nslots;
      const int i = tid >> 1;
      float freq = expf((float)(2*i) * (-9.210340371976184f / (float)D_));
      float ang  = (float)slot * freq;
      pe_s[tid] = (tid & 1) ? cosf(ang) : sinf(ang);
    }
    __syncthreads();
  }

  const int tx = tid & 15;
  const int ty = tid >> 4;

  float acc[8][8];
  #pragma unroll
  for (int i = 0; i < 8; ++i)
    #pragma unroll
    for (int j = 0; j < 8; ++j) acc[i][j] = 0.f;

  for (int k0 = 0; k0 < D_; k0 += 16) {
    #pragma unroll
    for (int r = 0; r < 2; ++r) {
      int idx = tid + r*256;
      int row = idx >> 2;
      int c4  = (idx & 3) << 2;
      float4 v = *reinterpret_cast<const float4*>(Xg + row*D_ + k0 + c4);
      if (PE) {
        v.x += pe_s[k0+c4+0]; v.y += pe_s[k0+c4+1];
        v.z += pe_s[k0+c4+2]; v.w += pe_s[k0+c4+3];
      }
      As[c4+0][row]=v.x; As[c4+1][row]=v.y; As[c4+2][row]=v.z; As[c4+3][row]=v.w;
    }
    #pragma unroll
    for (int r = 0; r < 2; ++r) {
      int idx = tid + r*256;
      int row = idx >> 5;
      int c4  = (idx & 31) << 2;
      *reinterpret_cast<float4*>(&Bs[row][c4]) =
          *reinterpret_cast<const float4*>(Wg + (size_t)(k0+row)*E_ + n0 + c4);
    }
    __syncthreads();

    #pragma unroll
    for (int kk = 0; kk < 16; ++kk) {
      float a[8], b[8];
      #pragma unroll
      for (int i = 0; i < 8; ++i) a[i] = As[kk][ty*8+i];
      #pragma unroll
      for (int j = 0; j < 8; ++j) b[j] = Bs[kk][tx*8+j];
      #pragma unroll
      for (int i = 0; i < 8; ++i)
        #pragma unroll
        for (int j = 0; j < 8; ++j) acc[i][j] += a[i]*b[j];
    }
    __syncthreads();
  }

  #pragma unroll
  for (int i = 0; i < 8; ++i) {
    int m = ty*8 + i;
    #pragma unroll
    for (int j = 0; j < 8; j += 4) {
      *reinterpret_cast<float4*>(Yg + (size_t)m*E_ + n0 + tx*8 + j) =
          make_float4(acc[i][j], acc[i][j+1], acc[i][j+2], acc[i][j+3]);
    }
  }
}

// ---------------------------------------------------------------------------
// Fused attention, warp-autonomous version.
// One block per (c,b,h), 128 threads. Warp w owns q rows 4w..4w+3, lane = k.
// Single __syncthreads (after tile load). Softmax fully in-warp (shfl).
// smem layout: Qs stride 64 (broadcast reads only), Ks/Vs stride 65
// (65 ≡ 1 mod 32 -> lane-distinct reads are conflict-free).
// ---------------------------------------------------------------------------
__device__ __forceinline__ float warp_max(float x) {
  #pragma unroll
  for (int s = 16; s > 0; s >>= 1)
    x = fmaxf(x, __shfl_xor_sync(0xffffffffu, x, s));
  return x;
}
__device__ __forceinline__ float warp_sum(float x) {
  #pragma unroll
  for (int s = 16; s > 0; s >>= 1)
    x += __shfl_xor_sync(0xffffffffu, x, s);
  return x;
}

__global__ void __launch_bounds__(128) attn_kernel(
    float* __restrict__ Q,              // in: query, out: attention output
    const float* __restrict__ K, const float* __restrict__ V)
{
  const int idx = blockIdx.x;           // ((c*B + b)*H + h)
  const int h = idx & (H_-1);
  const int b = (idx >> 3) & (B_-1);
  const int c = idx >> 10;

  __shared__ float Qs[NQ_][64];         // broadcast-only reads, no pad needed
  __shared__ float Ks[NK_][65];
  __shared__ float Vs[NK_][65];

  const int tid  = threadIdx.x;
  const int lane = tid & 31;
  const int w    = tid >> 5;

  // Q tile: 16 rows x 64 = 256 float4 (2/thread); fold inv_temp=0.125 in here.
  #pragma unroll
  for (int r = 0; r < 2; ++r) {
    int i = tid + r*128;
    int row = i >> 4;
    int c4  = (i & 15) << 2;
    float4 v = *reinterpret_cast<const float4*>(
        Q + ((size_t)((c*NQ_+row)*B_ + b))*E_ + h*A_ + c4);
    v.x *= 0.125f; v.y *= 0.125f; v.z *= 0.125f; v.w *= 0.125f;
    *reinterpret_cast<float4*>(&Qs[row][c4]) = v;
  }
  // K, V tiles: 32 rows x 64 = 512 float4 each (4/thread), scalar smem stores
  // (stride 65 is not 16B-aligned).
  #pragma unroll
  for (int r = 0; r < 4; ++r) {
    int i = tid + r*128;
    int row = i >> 4;
    int c4  = (i & 15) << 2;
    size_t off = ((size_t)((c*NK_+row)*B_ + b))*E_ + h*A_ + c4;
    float4 kv = *reinterpret_cast<const float4*>(K + off);
    Ks[row][c4+0]=kv.x; Ks[row][c4+1]=kv.y; Ks[row][c4+2]=kv.z; Ks[row][c4+3]=kv.w;
    float4 vv = *reinterpret_cast<const float4*>(V + off);
    Vs[row][c4+0]=vv.x; Vs[row][c4+1]=vv.y; Vs[row][c4+2]=vv.z; Vs[row][c4+3]=vv.w;
  }
  __syncthreads();

  // logits: lane computes l[j] = <Qs[q0+j], Ks[lane]> for 4 q rows.
  const int q0 = w * 4;
  float l0 = 0.f, l1 = 0.f, l2 = 0.f, l3 = 0.f;
  #pragma unroll
  for (int a = 0; a < A_; ++a) {
    float kv = Ks[lane][a];               // lane-distinct, conflict-free
    l0 += Qs[q0+0][a] * kv;               // broadcast
    l1 += Qs[q0+1][a] * kv;
    l2 += Qs[q0+2][a] * kv;
    l3 += Qs[q0+3][a] * kv;
  }

  // softmax across the warp (k dimension lives in lanes)
  float p0, p1, p2, p3;
  {
    float m0 = warp_max(l0), m1 = warp_max(l1), m2 = warp_max(l2), m3 = warp_max(l3);
    p0 = __expf(l0 - m0); p1 = __expf(l1 - m1);
    p2 = __expf(l2 - m2); p3 = __expf(l3 - m3);
    float s0 = warp_sum(p0), s1 = warp_sum(p1), s2 = warp_sum(p2), s3 = warp_sum(p3);
    p0 *= 1.f/s0; p1 *= 1.f/s1; p2 *= 1.f/s2; p3 *= 1.f/s3;
  }

  // PV: lane owns columns a=lane and a=lane+32; P broadcast via shfl.idx.
  float a00=0.f,a01=0.f,a10=0.f,a11=0.f,a20=0.f,a21=0.f,a30=0.f,a31=0.f;
  #pragma unroll
  for (int k = 0; k < NK_; ++k) {
    float v0 = Vs[k][lane];               // lane-distinct, conflict-free
    float v1 = Vs[k][lane+32];
    float pa = __shfl_sync(0xffffffffu, p0, k);
    a00 += pa*v0; a01 += pa*v1;
    float pb = __shfl_sync(0xffffffffu, p1, k);
    a10 += pb*v0; a11 += pb*v1;
    float pc = __shfl_sync(0xffffffffu, p2, k);
    a20 += pc*v0; a21 += pc*v1;
    float pd = __shfl_sync(0xffffffffu, p3, k);
    a30 += pd*v0; a31 += pd*v1;
  }

  // write back over this block's own query slice (coalesced 32-lane rows)
  {
    float* dst0 = Q + ((size_t)((c*NQ_+q0+0)*B_ + b))*E_ + h*A_;
    float* dst1 = Q + ((size_t)((c*NQ_+q0+1)*B_ + b))*E_ + h*A_;
    float* dst2 = Q + ((size_t)((c*NQ_+q0+2)*B_ + b))*E_ + h*A_;
    float* dst3 = Q + ((size_t)((c*NQ_+q0+3)*B_ + b))*E_ + h*A_;
    dst0[lane] = a00; dst0[lane+32] = a01;
    dst1[lane] = a10; dst1[lane+32] = a11;
    dst2[lane] = a20; dst2[lane+32] = a21;
    dst3[lane] = a30; dst3[lane+32] = a31;
  }
}

// ---------------------------------------------------------------------------
// Output projection: per (c,q): (128x512)@(512x64). 256 thr, 8x4 micro.
// ---------------------------------------------------------------------------
__global__ void __launch_bounds__(256) outproj_kernel(
    const float* __restrict__ Xa, const float* __restrict__ Wp,
    float* __restrict__ Y)
{
  const int g = blockIdx.x;                       // C*NQ
  const float* Ag = Xa + (size_t)g * (B_*E_);
  const float* Wg = Wp + (size_t)g * (E_*O_);
  float*       Yg = Y  + (size_t)g * (B_*O_);

  __shared__ float As[16][132];
  __shared__ float Bs[16][64];

  const int tid = threadIdx.x;
  const int tx = tid & 15;
  const int ty = tid >> 4;

  float acc[8][4];
  #pragma unroll
  for (int i = 0; i < 8; ++i)
    #pragma unroll
    for (int j = 0; j < 4; ++j) acc[i][j] = 0.f;

  for (int k0 = 0; k0 < E_; k0 += 16) {
    #pragma unroll
    for (int r = 0; r < 2; ++r) {
      int idx = tid + r*256;
      int row = idx >> 2;
      int c4  = (idx & 3) << 2;
      float4 v = *reinterpret_cast<const float4*>(Ag + (size_t)row*E_ + k0 + c4);
      As[c4+0][row]=v.x; As[c4+1][row]=v.y; As[c4+2][row]=v.z; As[c4+3][row]=v.w;
    }
    {
      int row = tid >> 4;
      int c4  = (tid & 15) << 2;
      *reinterpret_cast<float4*>(&Bs[row][c4]) =
          *reinterpret_cast<const float4*>(Wg + (size_t)(k0+row)*O_ + c4);
    }
    __syncthreads();

    #pragma unroll
    for (int kk = 0; kk < 16; ++kk) {
      float a[8], bb[4];
      #pragma unroll
      for (int i = 0; i < 8; ++i) a[i]  = As[kk][ty*8+i];
      #pragma unroll
      for (int j = 0; j < 4; ++j) bb[j] = Bs[kk][tx*4+j];
      #pragma unroll
      for (int i = 0; i < 8; ++i)
        #pragma unroll
        for (int j = 0; j < 4; ++j) acc[i][j] += a[i]*bb[j];
    }
    __syncthreads();
  }

  #pragma unroll
  for (int i = 0; i < 8; ++i) {
    int m = ty*8 + i;
    *reinterpret_cast<float4*>(Yg + (size_t)m*O_ + tx*4) =
        make_float4(acc[i][0], acc[i][1], acc[i][2], acc[i][3]);
  }
}

extern "C" void kernel_launch(void* const* d_in, const int* in_sizes, int n_in,
                              void* d_out, int out_size)
{
  const float* q  = (const float*)d_in[0];
  const float* k  = (const float*)d_in[1];
  const float* Wq = (const float*)d_in[2];
  const float* Wk = (const float*)d_in[3];
  const float* Wv = (const float*)d_in[4];
  const float* Wp = (const float*)d_in[5];
  float* out = (float*)d_out;

  float *gq, *gk, *gv;
  cudaGetSymbolAddress((void**)&gq, g_query);
  cudaGetSymbolAddress((void**)&gk, g_key);
  cudaGetSymbolAddress((void**)&gv, g_value);

  proj_kernel<true><<<dim3(4, C_*NQ_), 256>>>(q, Wq, gq, NQ_);
  proj_kernel<true><<<dim3(4, C_*NK_), 256>>>(k, Wk, gk, NK_);
  proj_kernel<true><<<dim3(4, C_*NK_), 256>>>(k, Wv, gv, NK_);
  attn_kernel<<<C_*B_*H_, 128>>>(gq, gk, gv);
  outproj_kernel<<<C_*NQ_, 256>>>(gq, Wp, out);
}